// round 7
// baseline (speedup 1.0000x reference)
#include <cuda_runtime.h>

// Problem dims (fixed by reference setup_inputs)
constexpr int B_ = 8;
constexpr int T_ = 100;
constexpr int S_ = 400;
constexpr int H_ = 256;

constexpr int TGT = 2;    // t-rows per attn CTA
constexpr int NTH = 224;  // attn threads (7 warps; 200 active, 2 s each)

// Scratch (device globals — no allocation allowed)
__device__ float g_WhT[B_ * H_ * S_];   // (enc @ W_h + b_attn)^T : [b][h][s]
__device__ float g_Ws [B_ * T_ * H_];   // dec @ W_s
__device__ float g_Apre[B_ * T_ * S_];  // A_prelim
__device__ float g_cov [B_ * T_ * S_];  // shifted cumsum of A_prelim

__device__ __forceinline__ float fast_tanh(float x) {
    float y;
    asm("tanh.approx.f32 %0, %1;" : "=f"(y) : "f"(x));
    return y;
}

// ---------------------------------------------------------------------------
// Fused projection GEMMs, 64x32 tiles, 256 thr, 2x4 per thread.
// blockIdx.y <  50 : WhT tile -> transposed store into g_WhT (+bias)
// blockIdx.y >= 50 : Ws  tile -> row-major store into g_Ws
// ---------------------------------------------------------------------------
__global__ __launch_bounds__(256) void dual_gemm(
    const float* __restrict__ enc, const float* __restrict__ W_h,
    const float* __restrict__ dec, const float* __restrict__ W_s,
    const float* __restrict__ bias)
{
    constexpr int K = H_, N = H_;
    bool isWh = blockIdx.y < 50;
    int  myTile = isWh ? blockIdx.y : (blockIdx.y - 50);
    int  M  = isWh ? B_ * S_ : B_ * T_;
    const float* A  = isWh ? enc : dec;
    const float* Bm = isWh ? W_h : W_s;

    int m0 = myTile * 64, n0 = blockIdx.x * 32;
    int tid = threadIdx.x;
    int tx = tid & 7;        // 8 groups of 4 cols
    int ty = tid >> 3;       // 32 rows of 2 m

    __shared__ float As[16][68];   // [k][m]
    __shared__ float Bs[16][36];   // [k][n]
    __shared__ float Ts[32][65];   // transposed tile [h][s] (WhT only)

    float acc[2][4] = {};

    int lm  = tid >> 2;      // 0..63 A row
    int lk4 = tid & 3;       // float4 idx in k-chunk
    int bkr = tid >> 4;      // 0..15 B k-row
    int bnc = tid & 15;      // 16 groups of 2 cols

    for (int k = 0; k < K; k += 16) {
        float4 av = make_float4(0.f, 0.f, 0.f, 0.f);
        int gm = m0 + lm;
        if (gm < M) av = *(const float4*)(A + (size_t)gm * K + k + lk4 * 4);
        As[lk4 * 4 + 0][lm] = av.x;
        As[lk4 * 4 + 1][lm] = av.y;
        As[lk4 * 4 + 2][lm] = av.z;
        As[lk4 * 4 + 3][lm] = av.w;
        float2 bv = *(const float2*)(Bm + (size_t)(k + bkr) * N + n0 + bnc * 2);
        Bs[bkr][bnc * 2 + 0] = bv.x;
        Bs[bkr][bnc * 2 + 1] = bv.y;
        __syncthreads();
#pragma unroll
        for (int kk = 0; kk < 16; kk++) {
            float2 a = *(float2*)&As[kk][ty * 2];
            float4 b = *(float4*)&Bs[kk][tx * 4];
            acc[0][0] = fmaf(a.x, b.x, acc[0][0]);
            acc[0][1] = fmaf(a.x, b.y, acc[0][1]);
            acc[0][2] = fmaf(a.x, b.z, acc[0][2]);
            acc[0][3] = fmaf(a.x, b.w, acc[0][3]);
            acc[1][0] = fmaf(a.y, b.x, acc[1][0]);
            acc[1][1] = fmaf(a.y, b.y, acc[1][1]);
            acc[1][2] = fmaf(a.y, b.z, acc[1][2]);
            acc[1][3] = fmaf(a.y, b.w, acc[1][3]);
        }
        __syncthreads();
    }

    if (isWh) {
        // bias add, transpose via SMEM, coalesced store to WhT.
#pragma unroll
        for (int j = 0; j < 4; j++) {
            float bi = bias[n0 + tx * 4 + j];
#pragma unroll
            for (int i = 0; i < 2; i++)
                Ts[tx * 4 + j][ty * 2 + i] = acc[i][j] + bi;
        }
        __syncthreads();
#pragma unroll
        for (int kk = 0; kk < 8; kk++) {
            int e  = tid + 256 * kk;
            int h  = e >> 6;          // 0..31
            int sl = e & 63;
            int m  = m0 + sl;
            int b  = m / S_;
            int s  = m - b * S_;
            g_WhT[(size_t)b * H_ * S_ + (size_t)(n0 + h) * S_ + s] = Ts[h][sl];
        }
    } else {
#pragma unroll
        for (int i = 0; i < 2; i++) {
            int gm = m0 + ty * 2 + i;
            if (gm < M) {
#pragma unroll
                for (int j = 0; j < 4; j++)
                    g_Ws[(size_t)gm * N + n0 + tx * 4 + j] = acc[i][j];
            }
        }
    }
}

// ---------------------------------------------------------------------------
// Batched SGEMM, 32x32 tile, 2x2 per thread (context).
// ---------------------------------------------------------------------------
__global__ __launch_bounds__(256) void sgemm32(
    const float* __restrict__ A, const float* __restrict__ Bm,
    float* __restrict__ C, int M, int N, int K,
    long long sA, long long sB, long long sC)
{
    int bz = blockIdx.z;
    A  += (size_t)bz * sA;
    Bm += (size_t)bz * sB;
    C  += (size_t)bz * sC;

    int m0 = blockIdx.y * 32, n0 = blockIdx.x * 32;
    int tid = threadIdx.x;
    int tx = tid & 15, ty = tid >> 4;

    __shared__ float As[32][17];
    __shared__ float Bs[16][33];

    float c00 = 0.f, c01 = 0.f, c10 = 0.f, c11 = 0.f;

    for (int k = 0; k < K; k += 16) {
#pragma unroll
        for (int i = 0; i < 2; i++) {
            int e = tid + i * 256;
            int m = e >> 4, kk = e & 15;
            int gm = m0 + m;
            As[m][kk] = (gm < M) ? A[(size_t)gm * K + k + kk] : 0.f;
            int kk2 = e >> 5, n = e & 31;
            Bs[kk2][n] = Bm[(size_t)(k + kk2) * N + n0 + n];
        }
        __syncthreads();
#pragma unroll
        for (int kk = 0; kk < 16; kk++) {
            float a0 = As[ty][kk], a1 = As[ty + 16][kk];
            float b0 = Bs[kk][tx], b1 = Bs[kk][tx + 16];
            c00 = fmaf(a0, b0, c00);
            c01 = fmaf(a0, b1, c01);
            c10 = fmaf(a1, b0, c10);
            c11 = fmaf(a1, b1, c11);
        }
        __syncthreads();
    }

    if (m0 + ty < M) {
        C[(size_t)(m0 + ty) * N + n0 + tx]      = c00;
        C[(size_t)(m0 + ty) * N + n0 + tx + 16] = c01;
    }
    if (m0 + ty + 16 < M) {
        C[(size_t)(m0 + ty + 16) * N + n0 + tx]      = c10;
        C[(size_t)(m0 + ty + 16) * N + n0 + tx + 16] = c11;
    }
}

// ---------------------------------------------------------------------------
// attn_pass v5: 2 s-values per thread via LDG.64; 224 threads (7 warps).
// Per h: 1 LDG.64 + 2 LDS.64 + 4 ADD + 4 MUFU + 4 FMA -> 2.75 instr/tanh.
// ---------------------------------------------------------------------------
template <bool PASS2>
__global__ __launch_bounds__(NTH) void attn_pass(
    const unsigned char* __restrict__ mask,
    const float* __restrict__ v,
    const float* __restrict__ wc,
    float* __restrict__ AoutParam,
    float* __restrict__ loss)
{
    __shared__ float2 sVW[H_];        // (v[h], wc[h])
    __shared__ float2 sWp[H_];        // (ws_t0[h], ws_t1[h])
    __shared__ float  sE[TGT][S_];
    __shared__ float  sCov[TGT][S_];
    __shared__ float  sRed[16];

    int tid = threadIdx.x;
    int b   = blockIdx.x / (T_ / TGT);
    int t0  = (blockIdx.x % (T_ / TGT)) * TGT;

    const float* ws0 = g_Ws + ((size_t)b * T_ + t0) * H_;
    for (int h = tid; h < H_; h += NTH) {
        sVW[h] = make_float2(v[h], PASS2 ? wc[h] : 0.f);
        sWp[h] = make_float2(ws0[h], ws0[H_ + h]);
    }
    if (PASS2) {
        const float* cv = g_cov + ((size_t)b * T_ + t0) * S_;
        float* flat = &sCov[0][0];
        for (int i = tid; i < TGT * S_; i += NTH) flat[i] = cv[i];
    }
    __syncthreads();

    if (tid < S_ / 2) {
        int s0 = tid * 2;
        const float2* whp = (const float2*)(g_WhT + (size_t)b * H_ * S_) + tid;
        bool mk0 = mask[b * S_ + s0]     != 0;
        bool mk1 = mask[b * S_ + s0 + 1] != 0;
        float c00 = 0.f, c01 = 0.f, c10 = 0.f, c11 = 0.f;
        if (PASS2) {
            c00 = sCov[0][s0];     c10 = sCov[1][s0];
            c01 = sCov[0][s0 + 1]; c11 = sCov[1][s0 + 1];
        }
        float a00 = 0.f, a10 = 0.f, a01 = 0.f, a11 = 0.f;
#pragma unroll 8
        for (int h = 0; h < H_; h++) {
            float2 wh = whp[(size_t)h * (S_ / 2)];
            float2 vw = sVW[h];
            float2 wp = sWp[h];
            float x00 = wh.x + wp.x;   // t0,s0
            float x10 = wh.x + wp.y;   // t1,s0
            float x01 = wh.y + wp.x;   // t0,s1
            float x11 = wh.y + wp.y;   // t1,s1
            if (PASS2) {
                x00 = fmaf(c00, vw.y, x00);
                x10 = fmaf(c10, vw.y, x10);
                x01 = fmaf(c01, vw.y, x01);
                x11 = fmaf(c11, vw.y, x11);
            }
            a00 = fmaf(vw.x, fast_tanh(x00), a00);
            a10 = fmaf(vw.x, fast_tanh(x10), a10);
            a01 = fmaf(vw.x, fast_tanh(x01), a01);
            a11 = fmaf(vw.x, fast_tanh(x11), a11);
        }
        float e00 = fminf(fmaxf(a00, -30.0f), 30.0f);
        float e10 = fminf(fmaxf(a10, -30.0f), 30.0f);
        float e01 = fminf(fmaxf(a01, -30.0f), 30.0f);
        float e11 = fminf(fmaxf(a11, -30.0f), 30.0f);
        *(float2*)&sE[0][s0] = make_float2(mk0 ? -1e30f : e00, mk1 ? -1e30f : e01);
        *(float2*)&sE[1][s0] = make_float2(mk0 ? -1e30f : e10, mk1 ? -1e30f : e11);
    }
    __syncthreads();

    int lane = tid & 31, wid = tid >> 5;  // 7 warps
    float lossAcc = 0.f;

#pragma unroll
    for (int r = 0; r < TGT; r++) {
        float m = -1e30f;
        for (int s = tid; s < S_; s += NTH) m = fmaxf(m, sE[r][s]);
#pragma unroll
        for (int o = 16; o; o >>= 1) m = fmaxf(m, __shfl_xor_sync(0xffffffffu, m, o));
        if (lane == 0) sRed[wid] = m;
        __syncthreads();
        if (wid == 0) {
            float mm = (lane < 7) ? sRed[lane] : -1e30f;
#pragma unroll
            for (int o = 16; o; o >>= 1) mm = fmaxf(mm, __shfl_xor_sync(0xffffffffu, mm, o));
            if (lane == 0) sRed[14] = mm;
        }
        __syncthreads();
        float rowMax = sRed[14];

        float sum = 0.f;
        for (int s = tid; s < S_; s += NTH) {
            float ex = __expf(sE[r][s] - rowMax);
            sE[r][s] = ex;
            sum += ex;
        }
#pragma unroll
        for (int o = 16; o; o >>= 1) sum += __shfl_xor_sync(0xffffffffu, sum, o);
        if (lane == 0) sRed[wid] = sum;
        __syncthreads();
        if (wid == 0) {
            float ss = (lane < 7) ? sRed[lane] : 0.f;
#pragma unroll
            for (int o = 16; o; o >>= 1) ss += __shfl_xor_sync(0xffffffffu, ss, o);
            if (lane == 0) sRed[15] = ss;
        }
        __syncthreads();
        float inv = 1.0f / fmaxf(sRed[15], 1e-30f);

        size_t rowOff = ((size_t)b * T_ + t0 + r) * S_;
        float* Aout = (PASS2 ? AoutParam : g_Apre) + rowOff;
        for (int s = tid; s < S_; s += NTH) {
            float a = sE[r][s] * inv;
            Aout[s] = a;
            if (PASS2) lossAcc += fminf(a, sCov[r][s]);
        }
        __syncthreads();
    }

    if (PASS2) {
#pragma unroll
        for (int o = 16; o; o >>= 1) lossAcc += __shfl_xor_sync(0xffffffffu, lossAcc, o);
        if (lane == 0) sRed[wid] = lossAcc;
        __syncthreads();
        if (tid == 0) {
            float p = 0.f;
#pragma unroll
            for (int i = 0; i < 7; i++) p += sRed[i];
            atomicAdd(loss, p * (1.0f / (B_ * T_)));
        }
    }
}

// ---------------------------------------------------------------------------
// cumsum: CTA = (b, 32 s-lanes); 128 threads = 32 s x 4 t-groups of 25.
// Coalesced, 25-deep MLP, smem 2-level exclusive scan. grid (13, 8) = 104.
// ---------------------------------------------------------------------------
__global__ __launch_bounds__(128) void cumsum_k(float* __restrict__ loss)
{
    constexpr int TSEG = 25;
    __shared__ float tot[4][32];

    if (blockIdx.x == 0 && blockIdx.y == 0 && threadIdx.x == 0) *loss = 0.f;

    int g  = threadIdx.x >> 5;       // t-group 0..3
    int sl = threadIdx.x & 31;
    int s  = blockIdx.x * 32 + sl;
    int b  = blockIdx.y;
    bool act = (s < S_);

    size_t base = (size_t)b * T_ * S_ + s;
    float vals[TSEG];
    if (act) {
#pragma unroll
        for (int u = 0; u < TSEG; u++)
            vals[u] = g_Apre[base + (size_t)(g * TSEG + u) * S_];
    } else {
#pragma unroll
        for (int u = 0; u < TSEG; u++) vals[u] = 0.f;
    }

    float run = 0.f;
#pragma unroll
    for (int u = 0; u < TSEG; u++) {
        float x = vals[u];
        vals[u] = run;
        run += x;
    }
    tot[g][sl] = run;
    __syncthreads();

    float off = 0.f;
#pragma unroll
    for (int gg = 0; gg < 3; gg++)
        if (gg < g) off += tot[gg][sl];

    if (act) {
#pragma unroll
        for (int u = 0; u < TSEG; u++)
            g_cov[base + (size_t)(g * TSEG + u) * S_] = off + vals[u];
    }
}

// ---------------------------------------------------------------------------
extern "C" void kernel_launch(void* const* d_in, const int* in_sizes, int n_in,
                              void* d_out, int out_size)
{
    const float*         dec    = (const float*)d_in[0];
    const float*         enc    = (const float*)d_in[1];
    const unsigned char* mask   = (const unsigned char*)d_in[2];
    const float*         W_h    = (const float*)d_in[3];
    const float*         W_s    = (const float*)d_in[4];
    const float*         w_c    = (const float*)d_in[5];
    const float*         v      = (const float*)d_in[6];
    const float*         b_attn = (const float*)d_in[7];

    float* out  = (float*)d_out;
    float* ctx  = out;
    float* Afin = out + (size_t)B_ * T_ * H_;
    float* loss = Afin + (size_t)B_ * T_ * S_;

    // Fused projections: 50 WhT tiles + 13 Ws tiles -> grid (8, 63)
    dual_gemm<<<dim3(H_ / 32, 63), 256>>>(enc, W_h, dec, W_s, b_attn);

    // Pass 1: A_prelim
    attn_pass<false><<<B_ * (T_ / TGT), NTH>>>(mask, v, nullptr, nullptr, nullptr);

    // Shifted cumsum over t (also zeroes loss slot)
    cumsum_k<<<dim3((S_ + 31) / 32, B_), 128>>>(loss);

    // Pass 2: A_final + cov_loss
    attn_pass<true><<<B_ * (T_ / TGT), NTH>>>(mask, v, w_c, Afin, loss);

    // context[b] = A_final[b] @ enc[b]
    sgemm32<<<dim3(H_ / 32, (T_ + 31) / 32, B_), 256>>>(
        Afin, enc, ctx, T_, H_, S_,
        (long long)T_ * S_, (long long)S_ * H_, (long long)T_ * H_);
}

// round 8
// speedup vs baseline: 1.1054x; 1.1054x over previous
#include <cuda_runtime.h>
#include <cuda_fp16.h>

// Problem dims (fixed by reference setup_inputs)
constexpr int B_ = 8;
constexpr int T_ = 100;
constexpr int S_ = 400;
constexpr int H_ = 256;

constexpr int TGT = 2;    // t-rows per attn CTA
constexpr int NTH = 416;  // attn threads (13 warps; 400 active s-lanes)

// Scratch (device globals — no allocation allowed)
__device__ float g_WhT[B_ * H_ * S_];   // (enc @ W_h + b_attn)^T : [b][h][s]
__device__ float g_Ws [B_ * T_ * H_];   // dec @ W_s
__device__ float g_Apre[B_ * T_ * S_];  // A_prelim
__device__ float g_cov [B_ * T_ * S_];  // shifted cumsum of A_prelim

// Packed tanh: one MUFU evaluates tanh for both t-rows. Inputs/accum stay f32.
__device__ __forceinline__ unsigned tanh2(unsigned x) {
    unsigned y;
    asm("tanh.approx.f16x2 %0, %1;" : "=r"(y) : "r"(x));
    return y;
}

// ---------------------------------------------------------------------------
// Fused projection GEMMs, 64x32 tiles, 256 thr, 2x4 per thread.
// blockIdx.y <  50 : WhT tile -> transposed store into g_WhT (+bias)
// blockIdx.y >= 50 : Ws  tile -> row-major store into g_Ws
// ---------------------------------------------------------------------------
__global__ __launch_bounds__(256) void dual_gemm(
    const float* __restrict__ enc, const float* __restrict__ W_h,
    const float* __restrict__ dec, const float* __restrict__ W_s,
    const float* __restrict__ bias)
{
    constexpr int K = H_, N = H_;
    bool isWh = blockIdx.y < 50;
    int  myTile = isWh ? blockIdx.y : (blockIdx.y - 50);
    int  M  = isWh ? B_ * S_ : B_ * T_;
    const float* A  = isWh ? enc : dec;
    const float* Bm = isWh ? W_h : W_s;

    int m0 = myTile * 64, n0 = blockIdx.x * 32;
    int tid = threadIdx.x;
    int tx = tid & 7;
    int ty = tid >> 3;

    __shared__ float As[16][68];
    __shared__ float Bs[16][36];
    __shared__ float Ts[32][65];

    float acc[2][4] = {};

    int lm  = tid >> 2;
    int lk4 = tid & 3;
    int bkr = tid >> 4;
    int bnc = tid & 15;

    for (int k = 0; k < K; k += 16) {
        float4 av = make_float4(0.f, 0.f, 0.f, 0.f);
        int gm = m0 + lm;
        if (gm < M) av = *(const float4*)(A + (size_t)gm * K + k + lk4 * 4);
        As[lk4 * 4 + 0][lm] = av.x;
        As[lk4 * 4 + 1][lm] = av.y;
        As[lk4 * 4 + 2][lm] = av.z;
        As[lk4 * 4 + 3][lm] = av.w;
        float2 bv = *(const float2*)(Bm + (size_t)(k + bkr) * N + n0 + bnc * 2);
        Bs[bkr][bnc * 2 + 0] = bv.x;
        Bs[bkr][bnc * 2 + 1] = bv.y;
        __syncthreads();
#pragma unroll
        for (int kk = 0; kk < 16; kk++) {
            float2 a = *(float2*)&As[kk][ty * 2];
            float4 b = *(float4*)&Bs[kk][tx * 4];
            acc[0][0] = fmaf(a.x, b.x, acc[0][0]);
            acc[0][1] = fmaf(a.x, b.y, acc[0][1]);
            acc[0][2] = fmaf(a.x, b.z, acc[0][2]);
            acc[0][3] = fmaf(a.x, b.w, acc[0][3]);
            acc[1][0] = fmaf(a.y, b.x, acc[1][0]);
            acc[1][1] = fmaf(a.y, b.y, acc[1][1]);
            acc[1][2] = fmaf(a.y, b.z, acc[1][2]);
            acc[1][3] = fmaf(a.y, b.w, acc[1][3]);
        }
        __syncthreads();
    }

    if (isWh) {
#pragma unroll
        for (int j = 0; j < 4; j++) {
            float bi = bias[n0 + tx * 4 + j];
#pragma unroll
            for (int i = 0; i < 2; i++)
                Ts[tx * 4 + j][ty * 2 + i] = acc[i][j] + bi;
        }
        __syncthreads();
#pragma unroll
        for (int kk = 0; kk < 8; kk++) {
            int e  = tid + 256 * kk;
            int h  = e >> 6;
            int sl = e & 63;
            int m  = m0 + sl;
            int b  = m / S_;
            int s  = m - b * S_;
            g_WhT[(size_t)b * H_ * S_ + (size_t)(n0 + h) * S_ + s] = Ts[h][sl];
        }
    } else {
#pragma unroll
        for (int i = 0; i < 2; i++) {
            int gm = m0 + ty * 2 + i;
            if (gm < M) {
#pragma unroll
                for (int j = 0; j < 4; j++)
                    g_Ws[(size_t)gm * N + n0 + tx * 4 + j] = acc[i][j];
            }
        }
    }
}

// ---------------------------------------------------------------------------
// Batched SGEMM, 32x32 tile, 2x2 per thread (context).
// ---------------------------------------------------------------------------
__global__ __launch_bounds__(256) void sgemm32(
    const float* __restrict__ A, const float* __restrict__ Bm,
    float* __restrict__ C, int M, int N, int K,
    long long sA, long long sB, long long sC)
{
    int bz = blockIdx.z;
    A  += (size_t)bz * sA;
    Bm += (size_t)bz * sB;
    C  += (size_t)bz * sC;

    int m0 = blockIdx.y * 32, n0 = blockIdx.x * 32;
    int tid = threadIdx.x;
    int tx = tid & 15, ty = tid >> 4;

    __shared__ float As[32][17];
    __shared__ float Bs[16][33];

    float c00 = 0.f, c01 = 0.f, c10 = 0.f, c11 = 0.f;

    for (int k = 0; k < K; k += 16) {
#pragma unroll
        for (int i = 0; i < 2; i++) {
            int e = tid + i * 256;
            int m = e >> 4, kk = e & 15;
            int gm = m0 + m;
            As[m][kk] = (gm < M) ? A[(size_t)gm * K + k + kk] : 0.f;
            int kk2 = e >> 5, n = e & 31;
            Bs[kk2][n] = Bm[(size_t)(k + kk2) * N + n0 + n];
        }
        __syncthreads();
#pragma unroll
        for (int kk = 0; kk < 16; kk++) {
            float a0 = As[ty][kk], a1 = As[ty + 16][kk];
            float b0 = Bs[kk][tx], b1 = Bs[kk][tx + 16];
            c00 = fmaf(a0, b0, c00);
            c01 = fmaf(a0, b1, c01);
            c10 = fmaf(a1, b0, c10);
            c11 = fmaf(a1, b1, c11);
        }
        __syncthreads();
    }

    if (m0 + ty < M) {
        C[(size_t)(m0 + ty) * N + n0 + tx]      = c00;
        C[(size_t)(m0 + ty) * N + n0 + tx + 16] = c01;
    }
    if (m0 + ty + 16 < M) {
        C[(size_t)(m0 + ty + 16) * N + n0 + tx]      = c10;
        C[(size_t)(m0 + ty + 16) * N + n0 + tx + 16] = c11;
    }
}

// ---------------------------------------------------------------------------
// attn_pass (R6 shape + f16x2 tanh): lane-per-s over WhT, two independent
// LDS float2 streams, 416 threads. One MUFU per (t-pair, h).
// ---------------------------------------------------------------------------
template <bool PASS2>
__global__ __launch_bounds__(NTH) void attn_pass(
    const unsigned char* __restrict__ mask,
    const float* __restrict__ v,
    const float* __restrict__ wc,
    float* __restrict__ AoutParam,
    float* __restrict__ loss)
{
    __shared__ float2 sVW[H_];        // (v[h], wc[h])
    __shared__ float2 sWp[H_];        // (ws_t0[h], ws_t1[h])
    __shared__ float  sE[TGT][S_];
    __shared__ float  sCov[TGT][S_];
    __shared__ float  sRed[16];

    int tid = threadIdx.x;
    int b   = blockIdx.x / (T_ / TGT);
    int t0  = (blockIdx.x % (T_ / TGT)) * TGT;

    const float* ws0 = g_Ws + ((size_t)b * T_ + t0) * H_;
    for (int h = tid; h < H_; h += NTH) {
        sVW[h] = make_float2(v[h], PASS2 ? wc[h] : 0.f);
        sWp[h] = make_float2(ws0[h], ws0[H_ + h]);
    }
    if (PASS2) {
        const float* cv = g_cov + ((size_t)b * T_ + t0) * S_;
        float* flat = &sCov[0][0];
        for (int i = tid; i < TGT * S_; i += NTH) flat[i] = cv[i];
    }
    __syncthreads();

    int s = tid;
    if (s < S_) {
        const float* whp = g_WhT + (size_t)b * H_ * S_ + s;
        bool mk = mask[b * S_ + s] != 0;
        float c0 = 0.f, c1 = 0.f;
        if (PASS2) { c0 = sCov[0][s]; c1 = sCov[1][s]; }
        float acc0 = 0.f, acc1 = 0.f;
#pragma unroll 8
        for (int h = 0; h < H_; h++) {
            float  wh = __ldg(whp + (size_t)h * S_);
            float2 vw = sVW[h];
            float2 wp = sWp[h];
            float x0 = wh + wp.x;
            float x1 = wh + wp.y;
            if (PASS2) {
                x0 = fmaf(c0, vw.y, x0);
                x1 = fmaf(c1, vw.y, x1);
            }
            // pack both t's argument, one MUFU tanh for the pair
            __half2 xh = __floats2half2_rn(x0, x1);
            unsigned th = tanh2(*(unsigned*)&xh);
            __half2 t2 = *(__half2*)&th;
            acc0 = fmaf(vw.x, __low2float(t2),  acc0);
            acc1 = fmaf(vw.x, __high2float(t2), acc1);
        }
        float e0 = fminf(fmaxf(acc0, -30.0f), 30.0f);
        float e1 = fminf(fmaxf(acc1, -30.0f), 30.0f);
        sE[0][s] = mk ? -1e30f : e0;
        sE[1][s] = mk ? -1e30f : e1;
    }
    __syncthreads();

    int lane = tid & 31, wid = tid >> 5;  // 13 warps
    float lossAcc = 0.f;

#pragma unroll
    for (int r = 0; r < TGT; r++) {
        float m = (tid < S_) ? sE[r][tid] : -1e30f;
#pragma unroll
        for (int o = 16; o; o >>= 1) m = fmaxf(m, __shfl_xor_sync(0xffffffffu, m, o));
        if (lane == 0) sRed[wid] = m;
        __syncthreads();
        if (wid == 0) {
            float mm = (lane < 13) ? sRed[lane] : -1e30f;
#pragma unroll
            for (int o = 16; o; o >>= 1) mm = fmaxf(mm, __shfl_xor_sync(0xffffffffu, mm, o));
            if (lane == 0) sRed[14] = mm;
        }
        __syncthreads();
        float rowMax = sRed[14];

        float ex = (tid < S_) ? __expf(sE[r][tid] - rowMax) : 0.f;
        float sum = ex;
#pragma unroll
        for (int o = 16; o; o >>= 1) sum += __shfl_xor_sync(0xffffffffu, sum, o);
        if (lane == 0) sRed[wid] = sum;
        __syncthreads();
        if (wid == 0) {
            float ss = (lane < 13) ? sRed[lane] : 0.f;
#pragma unroll
            for (int o = 16; o; o >>= 1) ss += __shfl_xor_sync(0xffffffffu, ss, o);
            if (lane == 0) sRed[15] = ss;
        }
        __syncthreads();
        float inv = 1.0f / fmaxf(sRed[15], 1e-30f);

        if (tid < S_) {
            float a = ex * inv;
            size_t rowOff = ((size_t)b * T_ + t0 + r) * S_;
            (PASS2 ? AoutParam : g_Apre)[rowOff + tid] = a;
            if (PASS2) lossAcc += fminf(a, sCov[r][tid]);
        }
        __syncthreads();
    }

    if (PASS2) {
#pragma unroll
        for (int o = 16; o; o >>= 1) lossAcc += __shfl_xor_sync(0xffffffffu, lossAcc, o);
        if (lane == 0) sRed[wid] = lossAcc;
        __syncthreads();
        if (tid == 0) {
            float p = 0.f;
#pragma unroll
            for (int i = 0; i < 13; i++) p += sRed[i];
            atomicAdd(loss, p * (1.0f / (B_ * T_)));
        }
    }
}

// ---------------------------------------------------------------------------
// cumsum: CTA = (b, 32 s-lanes); 128 threads = 32 s x 4 t-groups of 25.
// ---------------------------------------------------------------------------
__global__ __launch_bounds__(128) void cumsum_k(float* __restrict__ loss)
{
    constexpr int TSEG = 25;
    __shared__ float tot[4][32];

    if (blockIdx.x == 0 && blockIdx.y == 0 && threadIdx.x == 0) *loss = 0.f;

    int g  = threadIdx.x >> 5;
    int sl = threadIdx.x & 31;
    int s  = blockIdx.x * 32 + sl;
    int b  = blockIdx.y;
    bool act = (s < S_);

    size_t base = (size_t)b * T_ * S_ + s;
    float vals[TSEG];
    if (act) {
#pragma unroll
        for (int u = 0; u < TSEG; u++)
            vals[u] = g_Apre[base + (size_t)(g * TSEG + u) * S_];
    } else {
#pragma unroll
        for (int u = 0; u < TSEG; u++) vals[u] = 0.f;
    }

    float run = 0.f;
#pragma unroll
    for (int u = 0; u < TSEG; u++) {
        float x = vals[u];
        vals[u] = run;
        run += x;
    }
    tot[g][sl] = run;
    __syncthreads();

    float off = 0.f;
#pragma unroll
    for (int gg = 0; gg < 3; gg++)
        if (gg < g) off += tot[gg][sl];

    if (act) {
#pragma unroll
        for (int u = 0; u < TSEG; u++)
            g_cov[base + (size_t)(g * TSEG + u) * S_] = off + vals[u];
    }
}

// ---------------------------------------------------------------------------
extern "C" void kernel_launch(void* const* d_in, const int* in_sizes, int n_in,
                              void* d_out, int out_size)
{
    const float*         dec    = (const float*)d_in[0];
    const float*         enc    = (const float*)d_in[1];
    const unsigned char* mask   = (const unsigned char*)d_in[2];
    const float*         W_h    = (const float*)d_in[3];
    const float*         W_s    = (const float*)d_in[4];
    const float*         w_c    = (const float*)d_in[5];
    const float*         v      = (const float*)d_in[6];
    const float*         b_attn = (const float*)d_in[7];

    float* out  = (float*)d_out;
    float* ctx  = out;
    float* Afin = out + (size_t)B_ * T_ * H_;
    float* loss = Afin + (size_t)B_ * T_ * S_;

    // Fused projections: 50 WhT tiles + 13 Ws tiles -> grid (8, 63)
    dual_gemm<<<dim3(H_ / 32, 63), 256>>>(enc, W_h, dec, W_s, b_attn);

    // Pass 1: A_prelim
    attn_pass<false><<<B_ * (T_ / TGT), NTH>>>(mask, v, nullptr, nullptr, nullptr);

    // Shifted cumsum over t (also zeroes loss slot)
    cumsum_k<<<dim3((S_ + 31) / 32, B_), 128>>>(loss);

    // Pass 2: A_final + cov_loss
    attn_pass<true><<<B_ * (T_ / TGT), NTH>>>(mask, v, w_c, Afin, loss);

    // context[b] = A_final[b] @ enc[b]
    sgemm32<<<dim3(H_ / 32, (T_ + 31) / 32, B_), 256>>>(
        Afin, enc, ctx, T_, H_, S_,
        (long long)T_ * S_, (long long)S_ * H_, (long long)T_ * H_);
}